// round 8
// baseline (speedup 1.0000x reference)
#include <cuda_runtime.h>
#include <math.h>

#define S   48
#define MD  10
#define H   48
#define NF  60

// dynamic smem layout (floats)
#define CBUF    2880                    // per-warp chunk buffer (32 traj x 90)
#define OFF_W   0                       // W native [k][h] : 2880
#define OFF_B   2880                    // bias 48
#define OFF_LW  2928
#define OFF_LB  2976
#define OFF_C   3024                    // 4 warps x 2880
#define OFF_FT  (OFF_C + 4*CBUF)        // 14544 : 2 groups x 1920
#define FT_G    1920                    // 32 traj x 60 (stride 60, 16B-aligned rows)
#define SMEM_FLOATS (OFF_FT + 2*FT_G)   // 18384 floats = 73536 B

__device__ __forceinline__ float wsum(float v){
  #pragma unroll
  for(int o=16;o;o>>=1) v += __shfl_xor_sync(0xffffffffu,v,o);
  return v;
}
__device__ __forceinline__ float fsqrt_fast(float x){ return x * rsqrtf(x); }

__global__ __launch_bounds__(128)
void traj_fused(const float* __restrict__ coords, const int* __restrict__ lengths,
                const float* __restrict__ W, const float* __restrict__ bias,
                const float* __restrict__ ln_w, const float* __restrict__ ln_b,
                float* __restrict__ out, int B)
{
  extern __shared__ float sm[];
  int tid = threadIdx.x;

  // stage W (native [k][h] layout) + params
  {
    const float4* src = (const float4*)W;
    float4* dst = (float4*)(sm + OFF_W);
    #pragma unroll
    for (int i = tid; i < NF*H/4; i += 128) dst[i] = src[i];
    if (tid < H){ sm[OFF_B+tid]=bias[tid]; sm[OFF_LW+tid]=ln_w[tid]; sm[OFF_LB+tid]=ln_b[tid]; }
  }

  int w = tid >> 5, t = tid & 31;
  int group = w >> 1, role = w & 1;          // role 0 = warp A (rows 0-24), 1 = warp B (rows 23-47)
  int base = (blockIdx.x*2 + group)*32;
  int tmax = B - base; tmax = tmax < 0 ? 0 : (tmax > 32 ? 32 : tmax);
  int b = base + t;
  bool act = (t < tmax);
  int n = act ? lengths[b] : 4;
  int m = n - 1, half = m >> 1;

  float* cw = sm + OFF_C + w*CBUF;
  float* fg = sm + OFF_FT + group*FT_G;

  float cur[MD], pd[MD], su[MD], dv[MD];
  float pinv = 0.f;
  float sc=0.f, scq=0.f, s_dm=0.f, s_dmsq=0.f, s_f=0.f, s_s=0.f, s_usq=0.f;
  float s_curv=0.f, s_curvsq=0.f, s_cos=0.f, s_neg=0.f;
  float mx_dm=-INFINITY, mx_curv=-INFINITY, nmn_curv=-INFINITY, nmn_cos=-INFINITY;
  #pragma unroll
  for (int j=0;j<MD;j++){ su[j]=0.f; dv[j]=0.f; pd[j]=0.f; cur[j]=0.f; }

  int rbase  = role ? 23 : 0;
  int kmin   = role ? 24 : 0;    // first delta with stats
  int cosmin = role ? 24 : 1;    // first delta that closes a cos pair

  bool first = true;
  for (int c=0; c<3; c++){
    __syncwarp();
    int r0  = rbase + c*9;                 // starts 0,9,18 (+23 for B)
    int cnt = (c==2) ? 7 : 9;              // rows per chunk: 9,9,7 (total 25)
    int F2  = cnt*5;                       // float2 count per traj
    for (int tt=0; tt<tmax; tt++){
      const float2* src = (const float2*)(coords + (size_t)(base+tt)*(S*MD) + r0*MD);
      float2* dst = (float2*)(cw + tt*90);
      dst[t] = src[t];                     // t<=31 < 35 <= F2 always
      if (t+32 < F2) dst[t+32] = src[t+32];
    }
    __syncwarp();

    for (int r=0; r<cnt; r++){
      int gi = r0 + r;
      float nxt[MD];
      #pragma unroll
      for (int j2=0;j2<5;j2++){
        float2 p = *(const float2*)(cw + t*90 + r*MD + 2*j2);
        nxt[2*j2]=p.x; nxt[2*j2+1]=p.y;
      }
      // coord sums: A owns rows 0..24, B rows 25..47
      if ((gi < n) && (role==0 || gi>=25)){
        #pragma unroll
        for (int j=0;j<MD;j++){ sc += nxt[j]; scq = fmaf(nxt[j],nxt[j],scq); }
      }
      if (first){
        #pragma unroll
        for (int j=0;j<MD;j++) cur[j]=nxt[j];
        first = false;
        continue;
      }
      int k = gi - 1;
      float d[MD]; float dsq=0.f;
      #pragma unroll
      for (int j=0;j<MD;j++){ d[j]=nxt[j]-cur[j]; dsq=fmaf(d[j],d[j],dsq); }
      float rs   = rsqrtf(fmaxf(dsq,1e-30f));
      float dmag = (dsq>0.f) ? dsq*rs : 0.f;
      float inv  = __fdividef(1.f, fmaxf(dmag,1e-8f));
      bool kv = (k < m);

      if (k >= kmin && kv){
        s_dm += dmag; s_dmsq += dsq;
        if (k < half+1) s_f += dmag;
        if (k >= half)  s_s += dmag;
        mx_dm = fmaxf(mx_dm, dmag);
        #pragma unroll
        for (int j=0;j<MD;j++){ su[j] = fmaf(d[j],inv,su[j]); dv[j] += d[j]; }
        s_usq = fmaf(dsq, inv*inv, s_usq);
      }
      if (k >= cosmin){
        float dot=0.f;
        #pragma unroll
        for (int j=0;j<MD;j++) dot = fmaf(pd[j], d[j], dot);
        float cs = dot*pinv*inv, cv = 1.f-cs;
        if (kv){
          s_curv += cv; s_curvsq = fmaf(cv,cv,s_curvsq);
          mx_curv = fmaxf(mx_curv, cv); nmn_curv = fmaxf(nmn_curv, -cv);
          s_cos += cs; nmn_cos = fmaxf(nmn_cos, -cs);
          if (cs < 0.f) s_neg += 1.f;
        }
        if (role==0 && k<=9)                     // padded curvs q=k-1 in 0..8
          fg[t*60 + 51 + (k-1)] = kv ? cv : 0.f;
      }
      if (role==0 && k<3){                       // padded deltas (always valid, m>=3)
        #pragma unroll
        for (int j=0;j<MD;j++) fg[t*60 + 21 + k*MD + j] = d[j];
      }
      #pragma unroll
      for (int j=0;j<MD;j++){ pd[j]=d[j]; cur[j]=nxt[j]; }
      pinv = inv;
    }
  }

  // ---- exchange partials (A -> its dead chunk buffer), B combines + scalars ----
  float* pbuf = sm + OFF_C + (group*2)*CBUF;     // warp A's buffer
  if (role==0){
    pbuf[ 0*32+t]=sc;      pbuf[ 1*32+t]=scq;     pbuf[ 2*32+t]=s_dm;  pbuf[ 3*32+t]=s_dmsq;
    pbuf[ 4*32+t]=s_f;     pbuf[ 5*32+t]=s_s;     pbuf[ 6*32+t]=s_usq; pbuf[ 7*32+t]=s_curv;
    pbuf[ 8*32+t]=s_curvsq;pbuf[ 9*32+t]=s_cos;   pbuf[10*32+t]=s_neg;
    pbuf[11*32+t]=mx_dm;   pbuf[12*32+t]=mx_curv; pbuf[13*32+t]=nmn_curv; pbuf[14*32+t]=nmn_cos;
    #pragma unroll
    for (int j=0;j<MD;j++){ pbuf[(15+j)*32+t]=su[j]; pbuf[(25+j)*32+t]=dv[j]; }
  }
  __syncthreads();
  if (role==1){
    sc      += pbuf[ 0*32+t]; scq     += pbuf[ 1*32+t];
    s_dm    += pbuf[ 2*32+t]; s_dmsq  += pbuf[ 3*32+t];
    s_f     += pbuf[ 4*32+t]; s_s     += pbuf[ 5*32+t];
    s_usq   += pbuf[ 6*32+t]; s_curv  += pbuf[ 7*32+t];
    s_curvsq+= pbuf[ 8*32+t]; s_cos   += pbuf[ 9*32+t];
    s_neg   += pbuf[10*32+t];
    mx_dm    = fmaxf(mx_dm,   pbuf[11*32+t]);
    mx_curv  = fmaxf(mx_curv, pbuf[12*32+t]);
    nmn_curv = fmaxf(nmn_curv,pbuf[13*32+t]);
    nmn_cos  = fmaxf(nmn_cos, pbuf[14*32+t]);
    #pragma unroll
    for (int j=0;j<MD;j++){ su[j]+=pbuf[(15+j)*32+t]; dv[j]+=pbuf[(25+j)*32+t]; }

    float mf  = (float)m;
    float ncf = (float)(n-2);
    float cnt = (float)(n*MD);
    float rncf = __fdividef(1.f, ncf);

    float mean_coord = __fdividef(sc, cnt);
    float coord_var  = __fdividef(scq - cnt*mean_coord*mean_coord, cnt-1.f);
    float std_coord  = fsqrt_fast(fmaxf(coord_var,1e-30f));

    float mean_dm = __fdividef(s_dm, mf);
    float dm_var  = __fdividef(s_dmsq - mf*mean_dm*mean_dm, fmaxf(mf-1.f,1.f));
    float std_dm  = fsqrt_fast(fmaxf(dm_var,1e-30f));      // m>=3

    float mean_curv = s_curv * rncf;
    float curv_var  = __fdividef(s_curvsq - ncf*mean_curv*mean_curv, fmaxf(ncf-1.f,1.f));
    float std_curv  = (ncf>1.f) ? fsqrt_fast(fmaxf(curv_var,1e-30f)) : 0.f;

    float tsq=0.f, ssq=0.f;
    #pragma unroll
    for (int j=0;j<MD;j++){ tsq = fmaf(dv[j],dv[j],tsq); ssq = fmaf(su[j],su[j],ssq); }
    float total_disp = (tsq>0.f) ? fsqrt_fast(fmaxf(tsq,1e-30f)) : 0.f;

    float npairs      = mf*(mf-1.f)*0.5f;
    float parallelism = 0.5f*(ssq - s_usq)*__fdividef(1.f, fmaxf(npairs,1.f));

    float rpl = __fdividef(1.f, s_dm+1e-9f);
    float disp_ratio  = total_disp * rpl;
    float loop_score  = 1.f - total_disp * rpl;
    float fh  = __fdividef(s_f, (float)(half+1));
    float sh2 = __fdividef(s_s, (float)(m-half));
    float rfh = __fdividef(1.f, fh+1e-9f);
    float convergence = (fh-sh2)*rfh;
    float cascade     = (sh2-fh)*rfh;
    float mean_cos    = s_cos * rncf;
    float dir_changes = s_neg * __fdividef(1.f, fmaxf(ncf,1.f));
    float jump        = (mean_dm>1e-9f) ? __fdividef(mx_dm, mean_dm) : 1.f;

    float* fr = fg + t*60;
    fr[0]=total_disp;  fr[1]=s_dm;        fr[2]=disp_ratio;   fr[3]=(float)n*0.1f;
    fr[4]=mean_curv;   fr[5]=mx_curv;     fr[6]=std_curv;     fr[7]=mx_curv-(-nmn_curv);
    fr[8]=mean_cos;    fr[9]=-nmn_cos;    fr[10]=dir_changes; fr[11]=disp_ratio;
    fr[12]=loop_score; fr[13]=convergence;fr[14]=parallelism; fr[15]=jump;
    fr[16]=cascade;    fr[17]=mean_dm;    fr[18]=std_dm;      fr[19]=mean_coord;
    fr[20]=std_coord;
  }
  __syncthreads();

  // ---- batched GEMV (16 traj per warp) + LN + exact GELU ----
  const float* shW_ = sm + OFF_W;
  int toff = role*16;
  float bb0 = sm[OFF_B + t];
  float bb1 = (t<16) ? sm[OFF_B + 32 + t] : 0.f;
  float lw0 = sm[OFF_LW + t], lb0 = sm[OFF_LB + t];
  float lw1 = (t<16) ? sm[OFF_LW + 32 + t] : 0.f;
  float lb1 = (t<16) ? sm[OFF_LB + 32 + t] : 0.f;

  float h0a[16], h1a[16];
  #pragma unroll
  for (int tt=0;tt<16;tt++){ h0a[tt]=bb0; h1a[tt]=bb1; }

  #pragma unroll 1
  for (int k4=0; k4<15; k4++){
    float w00 = shW_[(4*k4+0)*H + t];
    float w01 = shW_[(4*k4+1)*H + t];
    float w02 = shW_[(4*k4+2)*H + t];
    float w03 = shW_[(4*k4+3)*H + t];
    float w10 = shW_[(4*k4+0)*H + 32 + t];   // garbage for t>=16, in-bounds, discarded
    float w11 = shW_[(4*k4+1)*H + 32 + t];
    float w12 = shW_[(4*k4+2)*H + 32 + t];
    float w13 = shW_[(4*k4+3)*H + 32 + t];
    #pragma unroll
    for (int tt=0;tt<16;tt++){
      float4 fv = *(const float4*)(fg + (toff+tt)*60 + 4*k4);
      h0a[tt] = fmaf(fv.x,w00, fmaf(fv.y,w01, fmaf(fv.z,w02, fmaf(fv.w,w03, h0a[tt]))));
      h1a[tt] = fmaf(fv.x,w10, fmaf(fv.y,w11, fmaf(fv.z,w12, fmaf(fv.w,w13, h1a[tt]))));
    }
  }

  #pragma unroll
  for (int tt=0;tt<16;tt++){
    int bo = base + toff + tt;
    float h0 = h0a[tt], h1 = h1a[tt];
    float ss = h0 + ((t<16) ? h1 : 0.f);
    float mu = wsum(ss)*(1.f/48.f);
    float d0 = h0-mu, d1 = h1-mu;
    float vs = d0*d0 + ((t<16) ? d1*d1 : 0.f);
    float var = wsum(vs)*(1.f/48.f);
    float iv  = rsqrtf(var+1e-5f);
    if (bo < B){
      float g0 = d0*iv*lw0 + lb0;
      out[(size_t)bo*H + t] = 0.5f*g0*(1.f+erff(g0*0.70710678118654752f));
      if (t<16){
        float g1 = d1*iv*lw1 + lb1;
        out[(size_t)bo*H + t+32] = 0.5f*g1*(1.f+erff(g1*0.70710678118654752f));
      }
    }
  }
}

extern "C" void kernel_launch(void* const* d_in, const int* in_sizes, int n_in,
                              void* d_out, int out_size) {
  const float* coords = (const float*)d_in[0];
  const int*   lengths= (const int*)  d_in[1];
  const float* W      = (const float*)d_in[2];
  const float* bias   = (const float*)d_in[3];
  const float* ln_w   = (const float*)d_in[4];
  const float* ln_b   = (const float*)d_in[5];
  float* out = (float*)d_out;
  int B = in_sizes[0] / (S*MD);

  size_t smem = (size_t)SMEM_FLOATS * sizeof(float);   // 73536 B
  cudaFuncSetAttribute(traj_fused, cudaFuncAttributeMaxDynamicSharedMemorySize, (int)smem);
  int grid = (B + 63) / 64;
  traj_fused<<<grid, 128, smem>>>(coords, lengths, W, bias, ln_w, ln_b, out, B);
}

// round 9
// speedup vs baseline: 1.0716x; 1.0716x over previous
#include <cuda_runtime.h>
#include <math.h>

#define S    48
#define MD   10
#define H    48
#define NF   60
#define MAXB 65536
#define CW   2240          // per-warp chunk buffer: 32 traj x 7 rows x 10 (stride 70)
#define WPAD 2944          // padded native-W smem floats (>= 59*48+64)

__device__ float g_feat[(size_t)MAXB * NF];

__device__ __forceinline__ float wsum(float v){
  #pragma unroll
  for(int o=16;o;o>>=1) v += __shfl_xor_sync(0xffffffffu,v,o);
  return v;
}
__device__ __forceinline__ float fsqrt_fast(float x){ return x * rsqrtf(x); }

// ============ featA: 32 trajectories per block, 4 row-split warps ============
__global__ __launch_bounds__(128)
void featA(const float* __restrict__ coords, const int* __restrict__ lengths, int B)
{
  __shared__ float smC[4][CW];     // chunk buffers; reused as partial-exchange scratch
  __shared__ float smF[32*NF];     // features, stride 60

  int tid = threadIdx.x;
  int r = tid >> 5, t = tid & 31;
  int base = blockIdx.x * 32;
  if (base >= B) return;
  int tmax = B - base; if (tmax > 32) tmax = 32;
  int b = base + t;
  bool act = (t < tmax);
  int n = act ? lengths[b] : 4;
  int m = n - 1, half = m >> 1;

  // row-split: warp r owns deltas [kmin, kend), rows staged [R0, R1]
  int kmin = (r==0) ? 0 : r*12;
  int R0   = (r==0) ? 0 : r*12 - 1;
  int R1   = (r==3) ? 47 : (r+1)*12;
  int nrows = R1 - R0 + 1;                 // 13,14,14,13
  int cosmin = (r==0) ? 1 : kmin;
  int ownlo = r*12, ownhi = r*12 + 12;     // coord-sum row ownership

  float* cw = smC[r];

  float cur[MD], pd[MD], su[MD], dv[MD];
  float pinv = 0.f;
  float sc=0.f, scq=0.f, s_dm=0.f, s_dmsq=0.f, s_f=0.f, s_s=0.f, s_usq=0.f;
  float s_curv=0.f, s_curvsq=0.f, s_cos=0.f, s_neg=0.f;
  float mx_dm=-INFINITY, mx_curv=-INFINITY, nmn_curv=-INFINITY, nmn_cos=-INFINITY;
  #pragma unroll
  for (int j=0;j<MD;j++){ su[j]=0.f; dv[j]=0.f; pd[j]=0.f; cur[j]=0.f; }

  bool first = true;
  #pragma unroll
  for (int chunk=0; chunk<2; chunk++){
    int c0  = R0 + chunk*7;
    int cnt = (chunk==0) ? 7 : (nrows-7);  // 6 or 7
    int F2  = cnt*5;                        // float2s per traj
    __syncwarp();
    for (int tt=0; tt<tmax; tt++){
      const float2* src = (const float2*)(coords + (size_t)(base+tt)*(S*MD) + c0*MD);
      float2* dst = (float2*)(cw + tt*70);
      if (t < F2)      dst[t]    = src[t];
      if (t+32 < F2)   dst[t+32] = src[t+32];
    }
    __syncwarp();

    for (int ri=0; ri<cnt; ri++){
      int gi = c0 + ri;
      float nxt[MD];
      #pragma unroll
      for (int j2=0;j2<5;j2++){
        float2 p = *(const float2*)(cw + t*70 + ri*MD + 2*j2);
        nxt[2*j2]=p.x; nxt[2*j2+1]=p.y;
      }
      if (gi >= ownlo && gi < ownhi && gi < n){
        #pragma unroll
        for (int j=0;j<MD;j++){ sc += nxt[j]; scq = fmaf(nxt[j],nxt[j],scq); }
      }
      if (first){
        #pragma unroll
        for (int j=0;j<MD;j++) cur[j]=nxt[j];
        first = false;
        continue;
      }
      int k = gi - 1;
      float d[MD]; float dsq=0.f;
      #pragma unroll
      for (int j=0;j<MD;j++){ d[j]=nxt[j]-cur[j]; dsq=fmaf(d[j],d[j],dsq); }
      float rs   = rsqrtf(fmaxf(dsq,1e-30f));
      float dmag = (dsq>0.f) ? dsq*rs : 0.f;
      float inv  = __fdividef(1.f, fmaxf(dmag,1e-8f));
      bool kv = (k < m);

      if (k >= kmin && kv){
        s_dm += dmag; s_dmsq += dsq;
        if (k < half+1) s_f += dmag;
        if (k >= half)  s_s += dmag;
        mx_dm = fmaxf(mx_dm, dmag);
        #pragma unroll
        for (int j=0;j<MD;j++){ su[j] = fmaf(d[j],inv,su[j]); dv[j] += d[j]; }
        s_usq = fmaf(dsq, inv*inv, s_usq);
      }
      if (k >= cosmin){
        float dot=0.f;
        #pragma unroll
        for (int j=0;j<MD;j++) dot = fmaf(pd[j], d[j], dot);
        float cs = dot*pinv*inv, cv = 1.f-cs;
        if (kv){
          s_curv += cv; s_curvsq = fmaf(cv,cv,s_curvsq);
          mx_curv = fmaxf(mx_curv, cv); nmn_curv = fmaxf(nmn_curv, -cv);
          s_cos += cs; nmn_cos = fmaxf(nmn_cos, -cs);
          if (cs < 0.f) s_neg += 1.f;
        }
        if (r==0 && k<=9)
          smF[t*NF + 51 + (k-1)] = kv ? cv : 0.f;
      }
      if (r==0 && k<3){
        #pragma unroll
        for (int j=0;j<MD;j++) smF[t*NF + 21 + k*MD + j] = d[j];
      }
      #pragma unroll
      for (int j=0;j<MD;j++){ pd[j]=d[j]; cur[j]=nxt[j]; }
      pinv = inv;
    }
  }

  // ---- partial exchange: warps 1..3 -> their dead chunk buffers ----
  if (r > 0){
    float* p = smC[r];
    p[ 0*32+t]=sc;      p[ 1*32+t]=scq;     p[ 2*32+t]=s_dm;   p[ 3*32+t]=s_dmsq;
    p[ 4*32+t]=s_f;     p[ 5*32+t]=s_s;     p[ 6*32+t]=s_usq;  p[ 7*32+t]=s_curv;
    p[ 8*32+t]=s_curvsq;p[ 9*32+t]=s_cos;   p[10*32+t]=s_neg;
    p[11*32+t]=mx_dm;   p[12*32+t]=mx_curv; p[13*32+t]=nmn_curv; p[14*32+t]=nmn_cos;
    #pragma unroll
    for (int j=0;j<MD;j++){ p[(15+j)*32+t]=su[j]; p[(25+j)*32+t]=dv[j]; }
  }
  __syncthreads();

  if (r == 0){
    #pragma unroll
    for (int ww=1; ww<4; ww++){
      const float* p = smC[ww];
      sc      += p[ 0*32+t]; scq     += p[ 1*32+t];
      s_dm    += p[ 2*32+t]; s_dmsq  += p[ 3*32+t];
      s_f     += p[ 4*32+t]; s_s     += p[ 5*32+t];
      s_usq   += p[ 6*32+t]; s_curv  += p[ 7*32+t];
      s_curvsq+= p[ 8*32+t]; s_cos   += p[ 9*32+t];
      s_neg   += p[10*32+t];
      mx_dm    = fmaxf(mx_dm,   p[11*32+t]);
      mx_curv  = fmaxf(mx_curv, p[12*32+t]);
      nmn_curv = fmaxf(nmn_curv,p[13*32+t]);
      nmn_cos  = fmaxf(nmn_cos, p[14*32+t]);
      #pragma unroll
      for (int j=0;j<MD;j++){ su[j]+=p[(15+j)*32+t]; dv[j]+=p[(25+j)*32+t]; }
    }

    float mf  = (float)m;
    float ncf = (float)(n-2);
    float cnt = (float)(n*MD);
    float rncf = __fdividef(1.f, ncf);

    float mean_coord = __fdividef(sc, cnt);
    float coord_var  = __fdividef(scq - cnt*mean_coord*mean_coord, cnt-1.f);
    float std_coord  = fsqrt_fast(fmaxf(coord_var,1e-30f));

    float mean_dm = __fdividef(s_dm, mf);
    float dm_var  = __fdividef(s_dmsq - mf*mean_dm*mean_dm, fmaxf(mf-1.f,1.f));
    float std_dm  = fsqrt_fast(fmaxf(dm_var,1e-30f));      // m>=3 always

    float mean_curv = s_curv * rncf;
    float curv_var  = __fdividef(s_curvsq - ncf*mean_curv*mean_curv, fmaxf(ncf-1.f,1.f));
    float std_curv  = (ncf>1.f) ? fsqrt_fast(fmaxf(curv_var,1e-30f)) : 0.f;

    float tsq=0.f, ssq=0.f;
    #pragma unroll
    for (int j=0;j<MD;j++){ tsq = fmaf(dv[j],dv[j],tsq); ssq = fmaf(su[j],su[j],ssq); }
    float total_disp = (tsq>0.f) ? fsqrt_fast(fmaxf(tsq,1e-30f)) : 0.f;

    float npairs      = mf*(mf-1.f)*0.5f;
    float parallelism = 0.5f*(ssq - s_usq)*__fdividef(1.f, fmaxf(npairs,1.f));

    float rpl = __fdividef(1.f, s_dm+1e-9f);
    float disp_ratio  = total_disp * rpl;
    float loop_score  = 1.f - total_disp * rpl;
    float fh  = __fdividef(s_f, (float)(half+1));
    float sh2 = __fdividef(s_s, (float)(m-half));
    float rfh = __fdividef(1.f, fh+1e-9f);
    float convergence = (fh-sh2)*rfh;
    float cascade     = (sh2-fh)*rfh;
    float mean_cos    = s_cos * rncf;
    float dir_changes = s_neg * __fdividef(1.f, fmaxf(ncf,1.f));
    float jump        = (mean_dm>1e-9f) ? __fdividef(mx_dm, mean_dm) : 1.f;

    float* fr = smF + t*NF;
    fr[0]=total_disp;  fr[1]=s_dm;        fr[2]=disp_ratio;   fr[3]=(float)n*0.1f;
    fr[4]=mean_curv;   fr[5]=mx_curv;     fr[6]=std_curv;     fr[7]=mx_curv-(-nmn_curv);
    fr[8]=mean_cos;    fr[9]=-nmn_cos;    fr[10]=dir_changes; fr[11]=disp_ratio;
    fr[12]=loop_score; fr[13]=convergence;fr[14]=parallelism; fr[15]=jump;
    fr[16]=cascade;    fr[17]=mean_dm;    fr[18]=std_dm;      fr[19]=mean_coord;
    fr[20]=std_coord;
  }
  __syncthreads();

  // ---- flush features (coalesced float4) ----
  float4* dst4 = (float4*)(g_feat + (size_t)base*NF);
  const float4* src4 = (const float4*)smF;
  int n4 = tmax * (NF/4);
  for (int i = tid; i < n4; i += 128) dst4[i] = src4[i];
}

// ============ gemvB: GEMV (60x48, native-layout W) + LN + exact GELU ============
#define GW 8
#define GT 4
__global__ __launch_bounds__(GW*32)
void gemvB(const float* __restrict__ W, const float* __restrict__ bias,
           const float* __restrict__ ln_w, const float* __restrict__ ln_b,
           float* __restrict__ out, int B)
{
  __shared__ float shW[WPAD];
  __shared__ float shB[H], shLw[H], shLb[H];
  __shared__ __align__(16) float fbuf[GW][GT*NF];

  int tid = threadIdx.x;
  {
    const float4* src = (const float4*)W;
    float4* dst = (float4*)shW;
    float4 z = make_float4(0.f,0.f,0.f,0.f);
    #pragma unroll
    for (int i = tid; i < WPAD/4; i += GW*32) dst[i] = (i < NF*H/4) ? src[i] : z;
    if (tid < H){ shB[tid]=bias[tid]; shLw[tid]=ln_w[tid]; shLb[tid]=ln_b[tid]; }
  }
  __syncthreads();

  int w = tid>>5, l = tid&31;
  int b0 = (blockIdx.x*GW + w)*GT;
  if (b0 >= B) return;
  int rem = B - b0; if (rem > GT) rem = GT;

  if (rem == GT){
    const float4* src = (const float4*)(g_feat + (size_t)b0*NF);
    float4* dst = (float4*)fbuf[w];
    if (l < 30){ dst[l] = src[l]; dst[l+30] = src[l+30]; }
  } else {
    const float* src = g_feat + (size_t)b0*NF;
    for (int e = l; e < rem*NF; e += 32) fbuf[w][e] = src[e];
  }
  __syncwarp();

  float h0a[GT], h1a[GT];
  #pragma unroll
  for (int tt=0;tt<GT;tt++){ h0a[tt]=shB[l]; h1a[tt]=(l<16)?shB[l+32]:0.f; }

  const float* fw = fbuf[w];
  #pragma unroll
  for (int k4=0; k4<15; k4++){
    float w00 = shW[(4*k4+0)*H + l];
    float w01 = shW[(4*k4+1)*H + l];
    float w02 = shW[(4*k4+2)*H + l];
    float w03 = shW[(4*k4+3)*H + l];
    float w10 = shW[(4*k4+0)*H + 32 + l];   // pad region for l>=16; discarded
    float w11 = shW[(4*k4+1)*H + 32 + l];
    float w12 = shW[(4*k4+2)*H + 32 + l];
    float w13 = shW[(4*k4+3)*H + 32 + l];
    #pragma unroll
    for (int tt=0;tt<GT;tt++){
      float4 fv = *(const float4*)(fw + tt*NF + 4*k4);
      h0a[tt] = fmaf(fv.x,w00, fmaf(fv.y,w01, fmaf(fv.z,w02, fmaf(fv.w,w03, h0a[tt]))));
      h1a[tt] = fmaf(fv.x,w10, fmaf(fv.y,w11, fmaf(fv.z,w12, fmaf(fv.w,w13, h1a[tt]))));
    }
  }

  #pragma unroll
  for (int tt=0;tt<GT;tt++){
    int b = b0 + tt;
    if (b >= B) break;
    float ss = h0a[tt] + ((l<16) ? h1a[tt] : 0.f);
    float mu = wsum(ss)*(1.f/48.f);
    float d0 = h0a[tt]-mu, d1 = h1a[tt]-mu;
    float vs = d0*d0 + ((l<16) ? d1*d1 : 0.f);
    float var = wsum(vs)*(1.f/48.f);
    float iv  = rsqrtf(var+1e-5f);
    float g0 = d0*iv*shLw[l]+shLb[l];
    out[(size_t)b*H + l] = 0.5f*g0*(1.f+erff(g0*0.70710678118654752f));
    if (l<16){
      float g1 = d1*iv*shLw[l+32]+shLb[l+32];
      out[(size_t)b*H + l+32] = 0.5f*g1*(1.f+erff(g1*0.70710678118654752f));
    }
  }
}

extern "C" void kernel_launch(void* const* d_in, const int* in_sizes, int n_in,
                              void* d_out, int out_size) {
  const float* coords = (const float*)d_in[0];
  const int*   lengths= (const int*)  d_in[1];
  const float* W      = (const float*)d_in[2];
  const float* bias   = (const float*)d_in[3];
  const float* ln_w   = (const float*)d_in[4];
  const float* ln_b   = (const float*)d_in[5];
  float* out = (float*)d_out;
  int B = in_sizes[0] / (S*MD);

  int gridA = (B + 31) / 32;
  featA<<<gridA, 128>>>(coords, lengths, B);
  int gridB = (B + GW*GT - 1) / (GW*GT);
  gemvB<<<gridB, GW*32>>>(W, bias, ln_w, ln_b, out, B);
}

// round 10
// speedup vs baseline: 1.4617x; 1.3641x over previous
#include <cuda_runtime.h>
#include <math.h>

#define S    48
#define MD   10
#define H    48
#define NF   60

// dynamic smem layout (floats)
#define OFF_W    0                      // padded native-layout W: 2944 (indices >=2880 are 0)
#define OFF_B    2944                   // bias 48
#define OFF_LW   2992
#define OFF_LB   3040
#define OFF_C    3088                   // 4 warps x 2240 (chunk bufs / partial exchange)
#define CWF      2240
#define OFF_F    (OFF_C + 4*CWF)        // 12048 : features 32 x 60
#define SMEM_FLOATS (OFF_F + 32*NF)     // 13968 floats = 55872 B

__device__ __forceinline__ float fsqrt_fast(float x){ return x * rsqrtf(x); }

__global__ __launch_bounds__(128)
void traj_fused(const float* __restrict__ coords, const int* __restrict__ lengths,
                const float* __restrict__ W, const float* __restrict__ bias,
                const float* __restrict__ ln_w, const float* __restrict__ ln_b,
                float* __restrict__ out, int B)
{
  extern __shared__ float sm[];
  int tid = threadIdx.x;

  // ---- stage W (native [k][h], zero-padded) + params ----
  {
    const float4* src = (const float4*)W;
    float4* dst = (float4*)(sm + OFF_W);
    float4 z = make_float4(0.f,0.f,0.f,0.f);
    #pragma unroll
    for (int i = tid; i < 736; i += 128) dst[i] = (i < NF*H/4) ? src[i] : z;
    if (tid < H){ sm[OFF_B+tid]=bias[tid]; sm[OFF_LW+tid]=ln_w[tid]; sm[OFF_LB+tid]=ln_b[tid]; }
  }

  int r = tid >> 5, t = tid & 31;
  int base = blockIdx.x * 32;
  if (base >= B) return;
  int tmax = B - base; if (tmax > 32) tmax = 32;
  int b = base + t;
  bool act = (t < tmax);
  int n = act ? lengths[b] : 4;
  int m = n - 1, half = m >> 1;

  // row-split: warp r owns deltas [kmin, ...), rows staged [R0, R1]
  int kmin = (r==0) ? 0 : r*12;
  int R0   = (r==0) ? 0 : r*12 - 1;
  int R1   = (r==3) ? 47 : (r+1)*12;
  int nrows = R1 - R0 + 1;                 // 13,14,14,13
  int cosmin = (r==0) ? 1 : kmin;
  int ownlo = r*12, ownhi = r*12 + 12;

  float* cw  = sm + OFF_C + r*CWF;
  float* smF = sm + OFF_F;

  float cur[MD], pd[MD], su[MD], dv[MD];
  float pinv = 0.f;
  float sc=0.f, scq=0.f, s_dm=0.f, s_dmsq=0.f, s_f=0.f, s_s=0.f, s_usq=0.f;
  float s_curv=0.f, s_curvsq=0.f, s_cos=0.f, s_neg=0.f;
  float mx_dm=-INFINITY, mx_curv=-INFINITY, nmn_curv=-INFINITY, nmn_cos=-INFINITY;
  #pragma unroll
  for (int j=0;j<MD;j++){ su[j]=0.f; dv[j]=0.f; pd[j]=0.f; cur[j]=0.f; }

  bool first = true;
  #pragma unroll
  for (int chunk=0; chunk<2; chunk++){
    int c0  = R0 + chunk*7;
    int cnt = (chunk==0) ? 7 : (nrows-7);   // 7 then 6/7
    int F2  = cnt*5;
    __syncwarp();
    if (tmax == 32){
      const float2* srcb = (const float2*)(coords + (size_t)base*(S*MD) + c0*MD);
      #pragma unroll 4
      for (int tt=0; tt<32; tt++){
        const float2* src = srcb + tt*(S*MD/2);
        float2* dst = (float2*)(cw + tt*70);
        float2 v0 = src[t];
        dst[t] = v0;
        if (t+32 < F2) dst[t+32] = src[t+32];
      }
    } else {
      for (int tt=0; tt<tmax; tt++){
        const float2* src = (const float2*)(coords + (size_t)(base+tt)*(S*MD) + c0*MD);
        float2* dst = (float2*)(cw + tt*70);
        if (t < F2)    dst[t]    = src[t];
        if (t+32 < F2) dst[t+32] = src[t+32];
      }
    }
    __syncwarp();

    for (int ri=0; ri<cnt; ri++){
      int gi = c0 + ri;
      float nxt[MD];
      #pragma unroll
      for (int j2=0;j2<5;j2++){
        float2 p = *(const float2*)(cw + t*70 + ri*MD + 2*j2);
        nxt[2*j2]=p.x; nxt[2*j2+1]=p.y;
      }
      if (gi >= ownlo && gi < ownhi && gi < n){
        #pragma unroll
        for (int j=0;j<MD;j++){ sc += nxt[j]; scq = fmaf(nxt[j],nxt[j],scq); }
      }
      if (first){
        #pragma unroll
        for (int j=0;j<MD;j++) cur[j]=nxt[j];
        first = false;
        continue;
      }
      int k = gi - 1;
      float d[MD]; float dsq=0.f;
      #pragma unroll
      for (int j=0;j<MD;j++){ d[j]=nxt[j]-cur[j]; dsq=fmaf(d[j],d[j],dsq); }
      float rs   = rsqrtf(fmaxf(dsq,1e-30f));
      float dmag = (dsq>0.f) ? dsq*rs : 0.f;
      float inv  = __fdividef(1.f, fmaxf(dmag,1e-8f));
      bool kv = (k < m);

      if (k >= kmin && kv){
        s_dm += dmag; s_dmsq += dsq;
        if (k < half+1) s_f += dmag;
        if (k >= half)  s_s += dmag;
        mx_dm = fmaxf(mx_dm, dmag);
        #pragma unroll
        for (int j=0;j<MD;j++){ su[j] = fmaf(d[j],inv,su[j]); dv[j] += d[j]; }
        s_usq = fmaf(dsq, inv*inv, s_usq);
      }
      if (k >= cosmin){
        float dot=0.f;
        #pragma unroll
        for (int j=0;j<MD;j++) dot = fmaf(pd[j], d[j], dot);
        float cs = dot*pinv*inv, cv = 1.f-cs;
        if (kv){
          s_curv += cv; s_curvsq = fmaf(cv,cv,s_curvsq);
          mx_curv = fmaxf(mx_curv, cv); nmn_curv = fmaxf(nmn_curv, -cv);
          s_cos += cs; nmn_cos = fmaxf(nmn_cos, -cs);
          if (cs < 0.f) s_neg += 1.f;
        }
        if (r==0 && k<=9)
          smF[t*NF + 51 + (k-1)] = kv ? cv : 0.f;
      }
      if (r==0 && k<3){
        #pragma unroll
        for (int j=0;j<MD;j++) smF[t*NF + 21 + k*MD + j] = d[j];
      }
      #pragma unroll
      for (int j=0;j<MD;j++){ pd[j]=d[j]; cur[j]=nxt[j]; }
      pinv = inv;
    }
  }

  // ---- partial exchange via dead chunk buffers ----
  if (r > 0){
    float* p = sm + OFF_C + r*CWF;
    p[ 0*32+t]=sc;      p[ 1*32+t]=scq;     p[ 2*32+t]=s_dm;   p[ 3*32+t]=s_dmsq;
    p[ 4*32+t]=s_f;     p[ 5*32+t]=s_s;     p[ 6*32+t]=s_usq;  p[ 7*32+t]=s_curv;
    p[ 8*32+t]=s_curvsq;p[ 9*32+t]=s_cos;   p[10*32+t]=s_neg;
    p[11*32+t]=mx_dm;   p[12*32+t]=mx_curv; p[13*32+t]=nmn_curv; p[14*32+t]=nmn_cos;
    #pragma unroll
    for (int j=0;j<MD;j++){ p[(15+j)*32+t]=su[j]; p[(25+j)*32+t]=dv[j]; }
  }
  __syncthreads();

  if (r == 0){
    #pragma unroll
    for (int ww=1; ww<4; ww++){
      const float* p = sm + OFF_C + ww*CWF;
      sc      += p[ 0*32+t]; scq     += p[ 1*32+t];
      s_dm    += p[ 2*32+t]; s_dmsq  += p[ 3*32+t];
      s_f     += p[ 4*32+t]; s_s     += p[ 5*32+t];
      s_usq   += p[ 6*32+t]; s_curv  += p[ 7*32+t];
      s_curvsq+= p[ 8*32+t]; s_cos   += p[ 9*32+t];
      s_neg   += p[10*32+t];
      mx_dm    = fmaxf(mx_dm,   p[11*32+t]);
      mx_curv  = fmaxf(mx_curv, p[12*32+t]);
      nmn_curv = fmaxf(nmn_curv,p[13*32+t]);
      nmn_cos  = fmaxf(nmn_cos, p[14*32+t]);
      #pragma unroll
      for (int j=0;j<MD;j++){ su[j]+=p[(15+j)*32+t]; dv[j]+=p[(25+j)*32+t]; }
    }

    float mf  = (float)m;
    float ncf = (float)(n-2);
    float cnt = (float)(n*MD);
    float rncf = __fdividef(1.f, ncf);

    float mean_coord = __fdividef(sc, cnt);
    float coord_var  = __fdividef(scq - cnt*mean_coord*mean_coord, cnt-1.f);
    float std_coord  = fsqrt_fast(fmaxf(coord_var,1e-30f));

    float mean_dm = __fdividef(s_dm, mf);
    float dm_var  = __fdividef(s_dmsq - mf*mean_dm*mean_dm, fmaxf(mf-1.f,1.f));
    float std_dm  = fsqrt_fast(fmaxf(dm_var,1e-30f));      // m>=3 always

    float mean_curv = s_curv * rncf;
    float curv_var  = __fdividef(s_curvsq - ncf*mean_curv*mean_curv, fmaxf(ncf-1.f,1.f));
    float std_curv  = (ncf>1.f) ? fsqrt_fast(fmaxf(curv_var,1e-30f)) : 0.f;

    float tsq=0.f, ssq=0.f;
    #pragma unroll
    for (int j=0;j<MD;j++){ tsq = fmaf(dv[j],dv[j],tsq); ssq = fmaf(su[j],su[j],ssq); }
    float total_disp = (tsq>0.f) ? fsqrt_fast(fmaxf(tsq,1e-30f)) : 0.f;

    float npairs      = mf*(mf-1.f)*0.5f;
    float parallelism = 0.5f*(ssq - s_usq)*__fdividef(1.f, fmaxf(npairs,1.f));

    float rpl = __fdividef(1.f, s_dm+1e-9f);
    float disp_ratio  = total_disp * rpl;
    float loop_score  = 1.f - total_disp * rpl;
    float fh  = __fdividef(s_f, (float)(half+1));
    float sh2 = __fdividef(s_s, (float)(m-half));
    float rfh = __fdividef(1.f, fh+1e-9f);
    float convergence = (fh-sh2)*rfh;
    float cascade     = (sh2-fh)*rfh;
    float mean_cos    = s_cos * rncf;
    float dir_changes = s_neg * __fdividef(1.f, fmaxf(ncf,1.f));
    float jump        = (mean_dm>1e-9f) ? __fdividef(mx_dm, mean_dm) : 1.f;

    float* fr = smF + t*NF;
    fr[0]=total_disp;  fr[1]=s_dm;        fr[2]=disp_ratio;   fr[3]=(float)n*0.1f;
    fr[4]=mean_curv;   fr[5]=mx_curv;     fr[6]=std_curv;     fr[7]=mx_curv-(-nmn_curv);
    fr[8]=mean_cos;    fr[9]=-nmn_cos;    fr[10]=dir_changes; fr[11]=disp_ratio;
    fr[12]=loop_score; fr[13]=convergence;fr[14]=parallelism; fr[15]=jump;
    fr[16]=cascade;    fr[17]=mean_dm;    fr[18]=std_dm;      fr[19]=mean_coord;
    fr[20]=std_coord;
  }
  __syncthreads();

  // ---- GEMV: warp r handles trajectories [r*8, r*8+8) of this group ----
  const float* shW_ = sm + OFF_W;
  int t0 = r*8;
  float bb0 = sm[OFF_B + t];
  float bb1 = (t<16) ? sm[OFF_B + 32 + t] : 0.f;
  float lw0 = sm[OFF_LW + t], lb0 = sm[OFF_LB + t];
  float lw1 = (t<16) ? sm[OFF_LW + 32 + t] : 0.f;
  float lb1 = (t<16) ? sm[OFF_LB + 32 + t] : 0.f;

  float h0a[8], h1a[8];
  #pragma unroll
  for (int tt=0;tt<8;tt++){ h0a[tt]=bb0; h1a[tt]=bb1; }

  #pragma unroll
  for (int k4=0; k4<15; k4++){
    float w00 = shW_[(4*k4+0)*H + t];
    float w01 = shW_[(4*k4+1)*H + t];
    float w02 = shW_[(4*k4+2)*H + t];
    float w03 = shW_[(4*k4+3)*H + t];
    float w10 = shW_[(4*k4+0)*H + 32 + t];   // pad/garbage for t>=16; discarded
    float w11 = shW_[(4*k4+1)*H + 32 + t];
    float w12 = shW_[(4*k4+2)*H + 32 + t];
    float w13 = shW_[(4*k4+3)*H + 32 + t];
    #pragma unroll
    for (int tt=0;tt<8;tt++){
      float4 fv = *(const float4*)(smF + (t0+tt)*NF + 4*k4);
      h0a[tt] = fmaf(fv.x,w00, fmaf(fv.y,w01, fmaf(fv.z,w02, fmaf(fv.w,w03, h0a[tt]))));
      h1a[tt] = fmaf(fv.x,w10, fmaf(fv.y,w11, fmaf(fv.z,w12, fmaf(fv.w,w13, h1a[tt]))));
    }
  }

  #pragma unroll
  for (int tt=0;tt<8;tt++){
    int bo = base + t0 + tt;
    float h0 = h0a[tt], h1 = h1a[tt];
    bool lo16 = (t<16);
    float ss = h0 + (lo16 ? h1 : 0.f);
    float sq = h0*h0 + (lo16 ? h1*h1 : 0.f);
    #pragma unroll
    for (int o=16;o;o>>=1){
      ss += __shfl_xor_sync(0xffffffffu, ss, o);
      sq += __shfl_xor_sync(0xffffffffu, sq, o);
    }
    float mu  = ss*(1.f/48.f);
    float var = sq*(1.f/48.f) - mu*mu;
    float iv  = rsqrtf(var+1e-5f);
    if (bo < B){
      float g0 = (h0-mu)*iv*lw0 + lb0;
      out[(size_t)bo*H + t] = 0.5f*g0*(1.f+erff(g0*0.70710678118654752f));
      if (lo16){
        float g1 = (h1-mu)*iv*lw1 + lb1;
        out[(size_t)bo*H + t+32] = 0.5f*g1*(1.f+erff(g1*0.70710678118654752f));
      }
    }
  }
}

extern "C" void kernel_launch(void* const* d_in, const int* in_sizes, int n_in,
                              void* d_out, int out_size) {
  const float* coords = (const float*)d_in[0];
  const int*   lengths= (const int*)  d_in[1];
  const float* W      = (const float*)d_in[2];
  const float* bias   = (const float*)d_in[3];
  const float* ln_w   = (const float*)d_in[4];
  const float* ln_b   = (const float*)d_in[5];
  float* out = (float*)d_out;
  int B = in_sizes[0] / (S*MD);

  size_t smem = (size_t)SMEM_FLOATS * sizeof(float);   // 55872 B
  cudaFuncSetAttribute(traj_fused, cudaFuncAttributeMaxDynamicSharedMemorySize, (int)smem);
  int grid = (B + 31) / 32;
  traj_fused<<<grid, 128, smem>>>(coords, lengths, W, bias, ln_w, ln_b, out, B);
}